// round 8
// baseline (speedup 1.0000x reference)
#include <cuda_runtime.h>
#include <cstdint>

// EmbeddingDropout: out[b,s,:] = weight[x[b,s],:] * rowmask(x[b,s])
// rowmask reproduces jax.random.bernoulli(jax.random.key(42), 0.9, (V,1)) / 0.9
// under jax_threefry_partitionable=True (modern JAX default):
//   (o0,o1) = threefry2x32(key=(0,42), counter=(i>>32, i&0xffffffff)), i = row
//   bits32  = o0 ^ o1                     <-- XOR fold for bit_width==32
//   u = bitcast((bits32>>9)|0x3f800000) - 1.0 ;  keep iff u < 0.9
// x indices are int32 (JAX x64 disabled).

#define D 1024            // embedding dim (floats)
#define THREADS 256       // 256 threads * float4 = 1024 floats per row

__device__ __forceinline__ uint32_t rotl32(uint32_t x, uint32_t d) {
    return (x << d) | (x >> (32u - d));
}

// Threefry-2x32 with key (0, 42); returns both output lanes.
__device__ __forceinline__ void threefry2x32_42(uint32_t c0, uint32_t c1,
                                                uint32_t& o0, uint32_t& o1) {
    const uint32_t ks0 = 0u;
    const uint32_t ks1 = 42u;
    const uint32_t ks2 = 0u ^ 42u ^ 0x1BD11BDAu;
    uint32_t ks[3] = {ks0, ks1, ks2};

    uint32_t x0 = c0 + ks0;
    uint32_t x1 = c1 + ks1;

    const uint32_t rotA[4] = {13u, 15u, 26u, 6u};
    const uint32_t rotB[4] = {17u, 29u, 16u, 24u};

    #pragma unroll
    for (int g = 0; g < 5; ++g) {
        const uint32_t* rot = (g & 1) ? rotB : rotA;
        #pragma unroll
        for (int r = 0; r < 4; ++r) {
            x0 += x1;
            x1 = rotl32(x1, rot[r]);
            x1 ^= x0;
        }
        x0 += ks[(g + 1) % 3];
        x1 += ks[(g + 2) % 3] + (uint32_t)(g + 1);
    }
    o0 = x0;
    o1 = x1;
}

// scale for vocab row v: 1/0.9 if kept, 0 if dropped.
__device__ __forceinline__ float row_scale(int v) {
    uint32_t o0, o1;
    threefry2x32_42(0u, (uint32_t)v, o0, o1);
    uint32_t bits = o0 ^ o1;   // partitionable 32-bit path: XOR fold of lanes
    // jax.random.uniform: bitcast((bits>>9) | 0x3f800000) - 1.0f  in [0,1)
    float u = __uint_as_float((bits >> 9) | 0x3f800000u) - 1.0f;
    return (u < 0.9f) ? (1.0f / 0.9f) : 0.0f;
}

__global__ void __launch_bounds__(THREADS)
EmbeddingDropout_29875792511459_kernel(const int* __restrict__ x,
                                       const float* __restrict__ weight,
                                       float* __restrict__ out,
                                       int vocab) {
    const int token = blockIdx.x;
    int v = x[token];                 // int32 index; L1-broadcast in block
    v = min(max(v, 0), vocab - 1);    // defensive clamp

    const float scale = row_scale(v);

    float4* dst = reinterpret_cast<float4*>(out + (size_t)token * D);
    const int t = threadIdx.x;

    if (scale == 0.0f) {
        dst[t] = make_float4(0.0f, 0.0f, 0.0f, 0.0f);
    } else {
        const float4* src =
            reinterpret_cast<const float4*>(weight + (size_t)v * D);
        float4 val = __ldg(&src[t]);
        val.x *= scale; val.y *= scale; val.z *= scale; val.w *= scale;
        dst[t] = val;
    }
}

extern "C" void kernel_launch(void* const* d_in, const int* in_sizes, int n_in,
                              void* d_out, int out_size) {
    const int* x        = (const int*)d_in[0];          // int32 [8,2048]
    const float* weight = (const float*)d_in[1];        // fp32 [50257,1024]
    float* out          = (float*)d_out;                // fp32 [8,2048,1024]

    const int n_tokens = in_sizes[0];                   // 16384
    const int vocab    = in_sizes[1] / D;               // 50257

    EmbeddingDropout_29875792511459_kernel<<<n_tokens, THREADS>>>(
        x, weight, out, vocab);
}

// round 9
// speedup vs baseline: 1.5255x; 1.5255x over previous
#include <cuda_runtime.h>
#include <cstdint>

// EmbeddingDropout: out[b,s,:] = weight[x[b,s],:] * rowmask(x[b,s])
// rowmask = jax.random.bernoulli(jax.random.key(42), 0.9, (V,1)) / 0.9 under
// jax_threefry_partitionable=True:
//   (o0,o1) = threefry2x32(key=(0,42), counter=(0, row)); bits = o0 ^ o1
//   u = bitcast((bits>>9)|0x3f800000) - 1.0 ;  keep iff u < 0.9
// x indices are int32.

#define D 1024            // embedding dim (floats)
#define THREADS 256       // one float4 per thread per token row
#define TPC 4             // tokens per CTA

__device__ __forceinline__ uint32_t rotl32(uint32_t x, uint32_t d) {
    return (x << d) | (x >> (32u - d));
}

// Threefry-2x32 with key (0, 42); returns both output lanes.
__device__ __forceinline__ void threefry2x32_42(uint32_t c0, uint32_t c1,
                                                uint32_t& o0, uint32_t& o1) {
    const uint32_t ks0 = 0u;
    const uint32_t ks1 = 42u;
    const uint32_t ks2 = 0u ^ 42u ^ 0x1BD11BDAu;
    uint32_t ks[3] = {ks0, ks1, ks2};

    uint32_t x0 = c0 + ks0;
    uint32_t x1 = c1 + ks1;

    const uint32_t rotA[4] = {13u, 15u, 26u, 6u};
    const uint32_t rotB[4] = {17u, 29u, 16u, 24u};

    #pragma unroll
    for (int g = 0; g < 5; ++g) {
        const uint32_t* rot = (g & 1) ? rotB : rotA;
        #pragma unroll
        for (int r = 0; r < 4; ++r) {
            x0 += x1;
            x1 = rotl32(x1, rot[r]);
            x1 ^= x0;
        }
        x0 += ks[(g + 1) % 3];
        x1 += ks[(g + 2) % 3] + (uint32_t)(g + 1);
    }
    o0 = x0;
    o1 = x1;
}

__device__ __forceinline__ float row_scale(int v) {
    uint32_t o0, o1;
    threefry2x32_42(0u, (uint32_t)v, o0, o1);
    uint32_t bits = o0 ^ o1;   // partitionable 32-bit path: XOR fold
    float u = __uint_as_float((bits >> 9) | 0x3f800000u) - 1.0f;
    return (u < 0.9f) ? (1.0f / 0.9f) : 0.0f;
}

__global__ void __launch_bounds__(THREADS)
EmbeddingDropout_29875792511459_kernel(const int* __restrict__ x,
                                       const float* __restrict__ weight,
                                       float* __restrict__ out,
                                       int vocab, int n_tokens) {
    __shared__ int   s_idx[TPC];
    __shared__ float s_scl[TPC];

    const int base = blockIdx.x * TPC;
    const int t = threadIdx.x;

    // Threads 0..TPC-1 each hash one token's row; everyone else idles here.
    if (t < TPC) {
        int tok = min(base + t, n_tokens - 1);
        int v = x[tok];
        v = min(max(v, 0), vocab - 1);
        s_idx[t] = v;
        s_scl[t] = row_scale(v);
    }
    __syncthreads();

    // Batch the 4 independent row loads front-to-back for MLP=4.
    float4 val[TPC];
    #pragma unroll
    for (int k = 0; k < TPC; ++k) {
        const float4* src =
            reinterpret_cast<const float4*>(weight + (size_t)s_idx[k] * D);
        val[k] = __ldg(&src[t]);
    }

    #pragma unroll
    for (int k = 0; k < TPC; ++k) {
        const float s = s_scl[k];
        float4 r = val[k];
        r.x *= s; r.y *= s; r.z *= s; r.w *= s;
        float4* dst =
            reinterpret_cast<float4*>(out + (size_t)(base + k) * D);
        __stcs(&dst[t], r);   // streaming store: don't pollute L2
    }
}

extern "C" void kernel_launch(void* const* d_in, const int* in_sizes, int n_in,
                              void* d_out, int out_size) {
    const int* x        = (const int*)d_in[0];          // int32 [8,2048]
    const float* weight = (const float*)d_in[1];        // fp32 [50257,1024]
    float* out          = (float*)d_out;                // fp32 [8,2048,1024]

    const int n_tokens = in_sizes[0];                   // 16384
    const int vocab    = in_sizes[1] / D;               // 50257
    const int n_blocks = (n_tokens + TPC - 1) / TPC;    // 4096

    EmbeddingDropout_29875792511459_kernel<<<n_blocks, THREADS>>>(
        x, weight, out, vocab, n_tokens);
}

// round 12
// speedup vs baseline: 1.6957x; 1.1115x over previous
#include <cuda_runtime.h>
#include <cstdint>

// EmbeddingDropout: out[b,s,:] = weight[x[b,s],:] * rowmask(x[b,s])
// rowmask = jax.random.bernoulli(jax.random.key(42), 0.9, (V,1)) / 0.9 under
// jax_threefry_partitionable=True:
//   (o0,o1) = threefry2x32(key=(0,42), counter=(0, row)); bits = o0 ^ o1
//   u = bitcast((bits>>9)|0x3f800000) - 1.0 ;  keep iff u < 0.9
// x indices are int32.

#define D 1024            // embedding dim (floats)
#define THREADS 256       // one float4 per thread per token row
#define TPC 8             // tokens per CTA (MLP depth)

__device__ __forceinline__ uint32_t rotl32(uint32_t x, uint32_t d) {
    return (x << d) | (x >> (32u - d));
}

// Threefry-2x32 with key (0, 42); returns both output lanes.
__device__ __forceinline__ void threefry2x32_42(uint32_t c0, uint32_t c1,
                                                uint32_t& o0, uint32_t& o1) {
    const uint32_t ks0 = 0u;
    const uint32_t ks1 = 42u;
    const uint32_t ks2 = 0u ^ 42u ^ 0x1BD11BDAu;
    uint32_t ks[3] = {ks0, ks1, ks2};

    uint32_t x0 = c0 + ks0;
    uint32_t x1 = c1 + ks1;

    const uint32_t rotA[4] = {13u, 15u, 26u, 6u};
    const uint32_t rotB[4] = {17u, 29u, 16u, 24u};

    #pragma unroll
    for (int g = 0; g < 5; ++g) {
        const uint32_t* rot = (g & 1) ? rotB : rotA;
        #pragma unroll
        for (int r = 0; r < 4; ++r) {
            x0 += x1;
            x1 = rotl32(x1, rot[r]);
            x1 ^= x0;
        }
        x0 += ks[(g + 1) % 3];
        x1 += ks[(g + 2) % 3] + (uint32_t)(g + 1);
    }
    o0 = x0;
    o1 = x1;
}

__device__ __forceinline__ float row_scale(int v) {
    uint32_t o0, o1;
    threefry2x32_42(0u, (uint32_t)v, o0, o1);
    uint32_t bits = o0 ^ o1;   // partitionable 32-bit path: XOR fold
    float u = __uint_as_float((bits >> 9) | 0x3f800000u) - 1.0f;
    return (u < 0.9f) ? (1.0f / 0.9f) : 0.0f;
}

__global__ void __launch_bounds__(THREADS)
EmbeddingDropout_29875792511459_kernel(const int* __restrict__ x,
                                       const float* __restrict__ weight,
                                       float* __restrict__ out,
                                       int vocab, int n_tokens) {
    __shared__ int   s_idx[TPC];
    __shared__ float s_scl[TPC];

    const int base = blockIdx.x * TPC;
    const int t = threadIdx.x;

    // Threads 0..TPC-1 each hash one token's row.
    if (t < TPC) {
        int tok = min(base + t, n_tokens - 1);
        int v = x[tok];
        v = min(max(v, 0), vocab - 1);
        s_idx[t] = v;
        s_scl[t] = row_scale(v);
    }
    __syncthreads();

    // Pull indices/scales into registers so the load batch is pure LDG.
    int   idx[TPC];
    float scl[TPC];
    #pragma unroll
    for (int k = 0; k < TPC; ++k) { idx[k] = s_idx[k]; scl[k] = s_scl[k]; }

    // Batch TPC independent row loads front-to-back for deep MLP.
    // Dropped rows (scale==0, warp-uniform) are predicated off.
    float4 val[TPC];
    #pragma unroll
    for (int k = 0; k < TPC; ++k) {
        if (scl[k] != 0.0f) {
            const float4* src =
                reinterpret_cast<const float4*>(weight + (size_t)idx[k] * D);
            val[k] = __ldg(&src[t]);
        } else {
            val[k] = make_float4(0.0f, 0.0f, 0.0f, 0.0f);
        }
    }

    #pragma unroll
    for (int k = 0; k < TPC; ++k) {
        const float s = scl[k];
        float4 r = val[k];
        r.x *= s; r.y *= s; r.z *= s; r.w *= s;
        float4* dst =
            reinterpret_cast<float4*>(out + (size_t)(base + k) * D);
        __stcs(&dst[t], r);   // streaming store: keep weight rows in L2
    }
}

extern "C" void kernel_launch(void* const* d_in, const int* in_sizes, int n_in,
                              void* d_out, int out_size) {
    const int* x        = (const int*)d_in[0];          // int32 [8,2048]
    const float* weight = (const float*)d_in[1];        // fp32 [50257,1024]
    float* out          = (float*)d_out;                // fp32 [8,2048,1024]

    const int n_tokens = in_sizes[0];                   // 16384
    const int vocab    = in_sizes[1] / D;               // 50257
    const int n_blocks = (n_tokens + TPC - 1) / TPC;    // 2048

    EmbeddingDropout_29875792511459_kernel<<<n_blocks, THREADS>>>(
        x, weight, out, vocab, n_tokens);
}